// round 9
// baseline (speedup 1.0000x reference)
#include <cuda_runtime.h>
#include <cuda_bf16.h>
#include <cstdint>

#define EDIM 256
#define NE 1024
#define HW 4096
#define N_TOK 65536
#define ZQ_ELEMS 16777216
#define OFF_LOSS 16777216
#define OFF_ZERO 16777217
#define OFF_IDX  16777218
#define MARGIN 0.10f

typedef unsigned long long ull;

// -------------------- device globals --------------------
__device__ __nv_bfloat16 g_ch[NE * EDIM];   // codebook bf16 high
__device__ __nv_bfloat16 g_cl[NE * EDIM];   // codebook bf16 residual
__device__ float g_cn[NE];                  // ||c||^2 fp32
__device__ ull            g_tc[N_TOK][8];   // per-slot packed candidate lists (4 x u16)
__device__ unsigned char  g_tcnt[N_TOK][8]; // per-slot candidate counts
__device__ int   g_idx[N_TOK];
__device__ float g_part[16384];

__device__ __forceinline__ unsigned fenc(float x){
    unsigned u = __float_as_uint(x);
    return (u & 0x80000000u) ? ~u : (u | 0x80000000u);
}

// mma.sync m16n8k16 bf16 -> f32 (Ampere-era PTX; valid on plain sm_103 target)
#define MMA16816(c, a, b) \
    asm volatile("mma.sync.aligned.m16n8k16.row.col.f32.bf16.bf16.f32 " \
        "{%0,%1,%2,%3}, {%4,%5,%6,%7}, {%8,%9}, {%0,%1,%2,%3};" \
        : "+f"((c)[0]), "+f"((c)[1]), "+f"((c)[2]), "+f"((c)[3]) \
        : "r"((a)[0]), "r"((a)[1]), "r"((a)[2]), "r"((a)[3]), \
          "r"((b)[0]), "r"((b)[1]))

// -------------------- smem layout for p1 (byte offsets) --------------------
// padded row stride: 264 bf16 = 528 B = 132 words (conflict-free frag loads)
#define SA_W 132
#define SM_ZH 0            // 128 x 528 = 67584
#define SM_ZL 67584        // 128 x 528
#define SM_CH 135168       // 64 x 528 = 33792
#define SM_CL 168960       // 64 x 528
#define P1_SMEM 202752

// -------------------- kernel 1: codebook prep (bf16 split + norms) --------------------
__global__ void prep_cb_kernel(const float* __restrict__ cb){
    __shared__ float red[256];
    int code = blockIdx.x, k = threadIdx.x;
    float v = cb[code * EDIM + k];
    __nv_bfloat16 h = __float2bfloat16(v);
    float hf = __bfloat162float(h);
    g_ch[code * EDIM + k] = h;
    g_cl[code * EDIM + k] = __float2bfloat16(v - hf);
    red[k] = v * v;
    __syncthreads();
    for (int s = 128; s > 0; s >>= 1){
        if (k < s) red[k] += red[k + s];
        __syncthreads();
    }
    if (k == 0) g_cn[code] = red[0];
}

// -------------------- kernel 2: HMMA approx distances + sound shortlist --------------------
// Block: 128 tokens x 1024 codes (16 passes of 64). 8 warps = 4(M) x 2(N).
// dot ~= zh*ch + zh*cl + zl*ch (one fp32 accumulator). dist~ = ||c||^2 - 2*dot.
// Per (warp,tig) slot: running min + <=4 candidate list over its 128 codes.
__global__ __launch_bounds__(256, 1)
void p1_kernel(const float* __restrict__ z){
    extern __shared__ char smem[];
    uint32_t* zh32 = (uint32_t*)(smem + SM_ZH);
    uint32_t* zl32 = (uint32_t*)(smem + SM_ZL);
    uint32_t* ch32 = (uint32_t*)(smem + SM_CH);
    uint32_t* cl32 = (uint32_t*)(smem + SM_CL);

    const int tid = threadIdx.x;
    const int lane = tid & 31, wid = tid >> 5;
    const int gid = lane >> 2, tig = lane & 3;
    const int wm = wid & 3, wn = wid >> 2;

    const int n0 = blockIdx.x << 7;
    const int b = n0 >> 12, hw0 = n0 & 4095;
    const float* zb = z + (size_t)b * (EDIM * HW) + hw0;

    // build z bf16 split tiles [tok][k], padded stride
    for (int i = tid; i < 8192; i += 256){
        int k = i >> 5, t4 = (i & 31) << 2;
        float4 v = *(const float4*)(zb + (size_t)k * HW + t4);
        float vv[4] = {v.x, v.y, v.z, v.w};
        #pragma unroll
        for (int j = 0; j < 4; j++){
            int tok = t4 + j;
            __nv_bfloat16 h = __float2bfloat16(vv[j]);
            float hf = __bfloat162float(h);
            __nv_bfloat16 l = __float2bfloat16(vv[j] - hf);
            *(__nv_bfloat16*)(smem + SM_ZH + tok * 528 + k * 2) = h;
            *(__nv_bfloat16*)(smem + SM_ZL + tok * 528 + k * 2) = l;
        }
    }

    float minv[4] = {1e30f, 1e30f, 1e30f, 1e30f};
    ull   clist[4] = {0, 0, 0, 0};
    int   cnt[4]  = {0, 0, 0, 0};

    for (int pass = 0; pass < 16; pass++){
        __syncthreads();   // prev pass's tile reads done
        // load 64-code tile (ch + cl) into smem
        {
            int row = tid >> 2, kc = (tid & 3) << 6;   // 64 k elems
            const uint4* sh = (const uint4*)(g_ch + (size_t)(pass * 64 + row) * EDIM + kc);
            const uint4* sl = (const uint4*)(g_cl + (size_t)(pass * 64 + row) * EDIM + kc);
            uint4* dh = (uint4*)(smem + SM_CH + row * 528 + kc * 2);
            uint4* dl = (uint4*)(smem + SM_CL + row * 528 + kc * 2);
            #pragma unroll
            for (int i = 0; i < 8; i++) dh[i] = sh[i];
            #pragma unroll
            for (int i = 0; i < 8; i++) dl[i] = sl[i];
        }
        __syncthreads();

        float acc[2][4][4];
        #pragma unroll
        for (int m = 0; m < 2; m++)
            #pragma unroll
            for (int nt = 0; nt < 4; nt++)
                #pragma unroll
                for (int r = 0; r < 4; r++) acc[m][nt][r] = 0.0f;

        #pragma unroll 4
        for (int ks = 0; ks < 16; ks++){
            uint32_t ah[2][4], al[2][4];
            #pragma unroll
            for (int m = 0; m < 2; m++){
                int r0 = (wm * 32 + m * 16 + gid) * SA_W + ks * 8 + tig;
                ah[m][0] = zh32[r0];
                ah[m][1] = zh32[r0 + 8 * SA_W];
                ah[m][2] = zh32[r0 + 4];
                ah[m][3] = zh32[r0 + 8 * SA_W + 4];
                al[m][0] = zl32[r0];
                al[m][1] = zl32[r0 + 8 * SA_W];
                al[m][2] = zl32[r0 + 4];
                al[m][3] = zl32[r0 + 8 * SA_W + 4];
            }
            uint32_t bh[4][2], bl[4][2];
            #pragma unroll
            for (int nt = 0; nt < 4; nt++){
                int c0 = (wn * 32 + nt * 8 + gid) * SA_W + ks * 8 + tig;
                bh[nt][0] = ch32[c0];
                bh[nt][1] = ch32[c0 + 4];
                bl[nt][0] = cl32[c0];
                bl[nt][1] = cl32[c0 + 4];
            }
            #pragma unroll
            for (int m = 0; m < 2; m++)
                #pragma unroll
                for (int nt = 0; nt < 4; nt++){
                    MMA16816(acc[m][nt], ah[m], bh[nt]);   // zh*ch
                    MMA16816(acc[m][nt], ah[m], bl[nt]);   // zh*cl
                    MMA16816(acc[m][nt], al[m], bh[nt]);   // zl*ch
                }
        }

        // epilogue: fold 64 codes into running min + candidate lists
        #pragma unroll
        for (int m = 0; m < 2; m++)
            #pragma unroll
            for (int rp = 0; rp < 2; rp++){
                const int ridx = m * 2 + rp;
                #pragma unroll
                for (int nt = 0; nt < 4; nt++)
                    #pragma unroll
                    for (int j = 0; j < 2; j++){
                        int code = pass * 64 + wn * 32 + nt * 8 + tig * 2 + j;
                        float dist = __ldg(&g_cn[code]) - 2.0f * acc[m][nt][rp * 2 + j];
                        if (dist < minv[ridx]) minv[ridx] = dist;
                        if (dist <= minv[ridx] + MARGIN){
                            if (cnt[ridx] < 4)
                                clist[ridx] |= (ull)(unsigned)code << (cnt[ridx] * 16);
                            cnt[ridx]++;
                        }
                    }
            }
    }

    // write per-slot results
    #pragma unroll
    for (int m = 0; m < 2; m++)
        #pragma unroll
        for (int rp = 0; rp < 2; rp++){
            const int ridx = m * 2 + rp;
            int tok = n0 + wm * 32 + m * 16 + gid + rp * 8;
            int slot = wn * 4 + tig;
            g_tc[tok][slot] = clist[ridx];
            g_tcnt[tok][slot] = (unsigned char)(cnt[ridx] > 255 ? 255 : cnt[ridx]);
        }
}

// -------------------- kernel 3: exact fp32 rescore of candidate union --------------------
// Block: 64 tokens, 4 threads/token. Same exact-score + tie-break semantics as R1 (passed).
__global__ void rescore_kernel(const float* __restrict__ z, const float* __restrict__ cb,
                               float* __restrict__ out){
    extern __shared__ char smem_raw[];
    float* zs = (float*)smem_raw;              // [256 k][64 tok]
    ull* keys = (ull*)(smem_raw + 65536);      // [64]
    int tid = threadIdx.x;
    int n0 = blockIdx.x << 6;
    int b = n0 >> 12, hw0 = n0 & 4095;
    const float* zb = z + (size_t)b * (EDIM * HW) + hw0;

    for (int i = tid; i < 4096; i += 256){
        int k = i >> 4, t4 = (i & 15) << 2;
        float4 v = *(const float4*)(zb + (size_t)k * HW + t4);
        *(float4*)(zs + k * 64 + t4) = v;
    }
    if (tid < 64) keys[tid] = ~0ULL;
    __syncthreads();

    int lt = tid >> 2, sub = tid & 3, n = n0 + lt;

    // overflow check: all 8 slot counts at once
    ull cnts8 = *(const ull*)g_tcnt[n];
    bool ovf = false;
    #pragma unroll
    for (int s = 0; s < 8; s++)
        if (((cnts8 >> (s * 8)) & 0xFF) > 4) ovf = true;

    ull bk = ~0ULL;
    if (ovf){
        for (int code = sub; code < NE; code += 4){
            const float4* crow = (const float4*)(cb + (size_t)code * EDIM);
            float acc = 0.0f;
            #pragma unroll 8
            for (int kk = 0; kk < 64; kk++){
                float4 cv = __ldg(crow + kk);
                int k = kk << 2;
                acc = fmaf(cv.x, zs[k * 64 + lt], acc);
                acc = fmaf(cv.y, zs[(k + 1) * 64 + lt], acc);
                acc = fmaf(cv.z, zs[(k + 2) * 64 + lt], acc);
                acc = fmaf(cv.w, zs[(k + 3) * 64 + lt], acc);
            }
            float dist = __ldg(&g_cn[code]) - 2.0f * acc;
            ull key = ((ull)fenc(dist) << 32) | (unsigned)code;
            if (key < bk) bk = key;
        }
    } else {
        #pragma unroll
        for (int si = 0; si < 2; si++){
            int slot = sub * 2 + si;
            int c = (int)((cnts8 >> (slot * 8)) & 0xFF);
            ull cl = g_tc[n][slot];
            for (int i = 0; i < c; i++){
                int code = (int)((cl >> (i * 16)) & 0xFFFF);
                const float4* crow = (const float4*)(cb + (size_t)code * EDIM);
                float acc = 0.0f;
                #pragma unroll 8
                for (int kk = 0; kk < 64; kk++){
                    float4 cv = __ldg(crow + kk);
                    int k = kk << 2;
                    acc = fmaf(cv.x, zs[k * 64 + lt], acc);
                    acc = fmaf(cv.y, zs[(k + 1) * 64 + lt], acc);
                    acc = fmaf(cv.z, zs[(k + 2) * 64 + lt], acc);
                    acc = fmaf(cv.w, zs[(k + 3) * 64 + lt], acc);
                }
                float dist = __ldg(&g_cn[code]) - 2.0f * acc;
                ull key = ((ull)fenc(dist) << 32) | (unsigned)code;
                if (key < bk) bk = key;
            }
        }
    }
    if (bk != ~0ULL) atomicMin(&keys[lt], bk);
    __syncthreads();
    if (tid < 64){
        int idx = (int)(unsigned)(keys[tid] & 0xFFFFFFFFULL);
        g_idx[n0 + tid] = idx;
        out[OFF_IDX + n0 + tid] = (float)idx;
    }
}

// -------------------- kernel 4: gather z_q + loss partials --------------------
__global__ void gather_kernel(const float* __restrict__ z, const float* __restrict__ cb,
                              float* __restrict__ out){
    __shared__ float red[8];
    int t = blockIdx.x * 256 + threadIdx.x;
    int o4 = t << 2;
    int b = o4 >> 20;
    int rem = o4 & 1048575;
    int c = rem >> 12;
    int hw = rem & 4095;
    int n = (b << 12) + hw;

    float4 zv = *(const float4*)(z + o4);
    int i0 = g_idx[n], i1 = g_idx[n + 1], i2 = g_idx[n + 2], i3 = g_idx[n + 3];
    float4 q;
    q.x = __ldg(cb + (size_t)i0 * EDIM + c);
    q.y = __ldg(cb + (size_t)i1 * EDIM + c);
    q.z = __ldg(cb + (size_t)i2 * EDIM + c);
    q.w = __ldg(cb + (size_t)i3 * EDIM + c);
    *(float4*)(out + o4) = q;

    float dx = q.x - zv.x, dy = q.y - zv.y, dz = q.z - zv.z, dw = q.w - zv.w;
    float s = dx * dx + dy * dy + dz * dz + dw * dw;

    #pragma unroll
    for (int off = 16; off; off >>= 1) s += __shfl_down_sync(0xffffffffu, s, off);
    int lane = threadIdx.x & 31, wid = threadIdx.x >> 5;
    if (lane == 0) red[wid] = s;
    __syncthreads();
    if (wid == 0){
        float v = (lane < 8) ? red[lane] : 0.0f;
        #pragma unroll
        for (int off = 4; off; off >>= 1) v += __shfl_down_sync(0xffffffffu, v, off);
        if (lane == 0) g_part[blockIdx.x] = v;
    }
}

// -------------------- kernel 5: deterministic final loss reduction --------------------
__global__ void finalize_kernel(float* __restrict__ out){
    __shared__ float red[256];
    int tid = threadIdx.x;
    float s = 0.0f;
    for (int j = 0; j < 64; j++) s += g_part[tid + (j << 8)];
    red[tid] = s;
    __syncthreads();
    for (int st = 128; st > 0; st >>= 1){
        if (tid < st) red[tid] += red[tid + st];
        __syncthreads();
    }
    if (tid == 0){
        out[OFF_LOSS] = red[0] / 16777216.0f;
        out[OFF_ZERO] = 0.0f;
    }
}

// -------------------- launch --------------------
extern "C" void kernel_launch(void* const* d_in, const int* in_sizes, int n_in,
                              void* d_out, int out_size){
    const float* z  = (const float*)d_in[0];
    const float* cb = (const float*)d_in[1];
    if (n_in >= 2 && in_sizes[0] == NE * EDIM && in_sizes[1] == ZQ_ELEMS){
        const float* t = z; z = cb; cb = t;
    }
    float* out = (float*)d_out;

    cudaFuncSetAttribute(p1_kernel, cudaFuncAttributeMaxDynamicSharedMemorySize, P1_SMEM);
    cudaFuncSetAttribute(rescore_kernel, cudaFuncAttributeMaxDynamicSharedMemorySize, 66048);

    prep_cb_kernel<<<NE, 256>>>(cb);
    p1_kernel<<<N_TOK / 128, 256, P1_SMEM>>>(z);
    rescore_kernel<<<N_TOK / 64, 256, 66048>>>(z, cb, out);
    gather_kernel<<<ZQ_ELEMS / 1024, 256>>>(z, cb, out);
    finalize_kernel<<<1, 256>>>(out);
}

// round 13
// speedup vs baseline: 19.2178x; 19.2178x over previous
#include <cuda_runtime.h>
#include <cuda_bf16.h>
#include <cstdint>

#define EDIM 256
#define NE 1024
#define HW 4096
#define N_TOK 65536
#define ZQ_ELEMS 16777216
#define OFF_LOSS 16777216
#define OFF_ZERO 16777217
#define OFF_IDX  16777218
#define MARGIN 0.10f

typedef unsigned long long ull;

// -------------------- device globals --------------------
__device__ __nv_bfloat16 g_ch[NE * EDIM];    // codebook bf16 high
__device__ __nv_bfloat16 g_cl[NE * EDIM];    // codebook bf16 residual
__device__ float g_cn[NE];                   // ||c||^2 fp32
__device__ float g_dist[(size_t)N_TOK * NE]; // approx distances (256 MB)
__device__ unsigned short g_cand[N_TOK][8];  // candidate codes per token
__device__ unsigned char  g_ccnt[N_TOK];     // candidate count per token
__device__ int   g_idx[N_TOK];
__device__ float g_part[16384];

__device__ __forceinline__ unsigned fenc(float x){
    unsigned u = __float_as_uint(x);
    return (u & 0x80000000u) ? ~u : (u | 0x80000000u);
}

// mma.sync m16n8k16 bf16 -> f32 (Ampere-era PTX; valid on plain sm_103 target)
#define MMA16816(c, a, b) \
    asm volatile("mma.sync.aligned.m16n8k16.row.col.f32.bf16.bf16.f32 " \
        "{%0,%1,%2,%3}, {%4,%5,%6,%7}, {%8,%9}, {%0,%1,%2,%3};" \
        : "+f"((c)[0]), "+f"((c)[1]), "+f"((c)[2]), "+f"((c)[3]) \
        : "r"((a)[0]), "r"((a)[1]), "r"((a)[2]), "r"((a)[3]), \
          "r"((b)[0]), "r"((b)[1]))

// -------------------- smem layout for p1 (byte offsets) --------------------
// padded row stride: 264 bf16 = 528 B = 132 words (conflict-free frag loads)
#define SA_W 132
#define SM_ZH 0            // 128 x 528 = 67584
#define SM_ZL 67584        // 128 x 528
#define SM_CH 135168       // 64 x 528 = 33792
#define SM_CL 168960       // 64 x 528
#define P1_SMEM 202752

// -------------------- kernel 1: codebook prep (bf16 split + norms) --------------------
__global__ void prep_cb_kernel(const float* __restrict__ cb){
    __shared__ float red[256];
    int code = blockIdx.x, k = threadIdx.x;
    float v = cb[code * EDIM + k];
    __nv_bfloat16 h = __float2bfloat16(v);
    float hf = __bfloat162float(h);
    g_ch[code * EDIM + k] = h;
    g_cl[code * EDIM + k] = __float2bfloat16(v - hf);
    red[k] = v * v;
    __syncthreads();
    for (int s = 128; s > 0; s >>= 1){
        if (k < s) red[k] += red[k + s];
        __syncthreads();
    }
    if (k == 0) g_cn[code] = red[0];
}

// -------------------- kernel 2: HMMA approx distances -> g_dist --------------------
// Block: 128 tokens x 1024 codes (16 passes of 64). 8 warps = 4(M) x 2(N).
// dot ~= zh*ch + zh*cl + zl*ch (fp32 accum). dist~ = ||c||^2 - 2*dot.
// (MMA core + fragment indexing validated in R9: indices bit-identical to exact.)
__global__ __launch_bounds__(256, 1)
void p1_kernel(const float* __restrict__ z){
    extern __shared__ char smem[];
    uint32_t* zh32 = (uint32_t*)(smem + SM_ZH);
    uint32_t* zl32 = (uint32_t*)(smem + SM_ZL);
    uint32_t* ch32 = (uint32_t*)(smem + SM_CH);
    uint32_t* cl32 = (uint32_t*)(smem + SM_CL);

    const int tid = threadIdx.x;
    const int lane = tid & 31, wid = tid >> 5;
    const int gid = lane >> 2, tig = lane & 3;
    const int wm = wid & 3, wn = wid >> 2;

    const int n0 = blockIdx.x << 7;
    const int b = n0 >> 12, hw0 = n0 & 4095;
    const float* zb = z + (size_t)b * (EDIM * HW) + hw0;

    // build z bf16 split tiles [tok][k], padded stride
    for (int i = tid; i < 8192; i += 256){
        int k = i >> 5, t4 = (i & 31) << 2;
        float4 v = *(const float4*)(zb + (size_t)k * HW + t4);
        float vv[4] = {v.x, v.y, v.z, v.w};
        #pragma unroll
        for (int j = 0; j < 4; j++){
            int tok = t4 + j;
            __nv_bfloat16 h = __float2bfloat16(vv[j]);
            float hf = __bfloat162float(h);
            __nv_bfloat16 l = __float2bfloat16(vv[j] - hf);
            *(__nv_bfloat16*)(smem + SM_ZH + tok * 528 + k * 2) = h;
            *(__nv_bfloat16*)(smem + SM_ZL + tok * 528 + k * 2) = l;
        }
    }

    for (int pass = 0; pass < 16; pass++){
        __syncthreads();   // prev pass's tile reads done
        // load 64-code tile (ch + cl) into smem
        {
            int row = tid >> 2, kc = (tid & 3) << 6;
            const uint4* sh = (const uint4*)(g_ch + (size_t)(pass * 64 + row) * EDIM + kc);
            const uint4* sl = (const uint4*)(g_cl + (size_t)(pass * 64 + row) * EDIM + kc);
            uint4* dh = (uint4*)(smem + SM_CH + row * 528 + kc * 2);
            uint4* dl = (uint4*)(smem + SM_CL + row * 528 + kc * 2);
            #pragma unroll
            for (int i = 0; i < 8; i++) dh[i] = sh[i];
            #pragma unroll
            for (int i = 0; i < 8; i++) dl[i] = sl[i];
        }
        __syncthreads();

        float acc[2][4][4];
        #pragma unroll
        for (int m = 0; m < 2; m++)
            #pragma unroll
            for (int nt = 0; nt < 4; nt++)
                #pragma unroll
                for (int r = 0; r < 4; r++) acc[m][nt][r] = 0.0f;

        #pragma unroll 4
        for (int ks = 0; ks < 16; ks++){
            uint32_t ah[2][4], al[2][4];
            #pragma unroll
            for (int m = 0; m < 2; m++){
                int r0 = (wm * 32 + m * 16 + gid) * SA_W + ks * 8 + tig;
                ah[m][0] = zh32[r0];
                ah[m][1] = zh32[r0 + 8 * SA_W];
                ah[m][2] = zh32[r0 + 4];
                ah[m][3] = zh32[r0 + 8 * SA_W + 4];
                al[m][0] = zl32[r0];
                al[m][1] = zl32[r0 + 8 * SA_W];
                al[m][2] = zl32[r0 + 4];
                al[m][3] = zl32[r0 + 8 * SA_W + 4];
            }
            uint32_t bh[4][2], bl[4][2];
            #pragma unroll
            for (int nt = 0; nt < 4; nt++){
                int c0 = (wn * 32 + nt * 8 + gid) * SA_W + ks * 8 + tig;
                bh[nt][0] = ch32[c0];
                bh[nt][1] = ch32[c0 + 4];
                bl[nt][0] = cl32[c0];
                bl[nt][1] = cl32[c0 + 4];
            }
            #pragma unroll
            for (int m = 0; m < 2; m++)
                #pragma unroll
                for (int nt = 0; nt < 4; nt++){
                    MMA16816(acc[m][nt], ah[m], bh[nt]);   // zh*ch
                    MMA16816(acc[m][nt], ah[m], bl[nt]);   // zh*cl
                    MMA16816(acc[m][nt], al[m], bh[nt]);   // zl*ch
                }
        }

        // epilogue: write approx distances
        #pragma unroll
        for (int m = 0; m < 2; m++)
            #pragma unroll
            for (int rp = 0; rp < 2; rp++){
                int tok = n0 + wm * 32 + m * 16 + gid + rp * 8;
                #pragma unroll
                for (int nt = 0; nt < 4; nt++)
                    #pragma unroll
                    for (int j = 0; j < 2; j++){
                        int code = pass * 64 + wn * 32 + nt * 8 + tig * 2 + j;
                        float dist = __ldg(&g_cn[code]) - 2.0f * acc[m][nt][rp * 2 + j];
                        g_dist[(size_t)tok * NE + code] = dist;
                    }
            }
    }
}

// -------------------- kernel 3: candidate collection vs FINAL approx min --------------------
// One warp per token: min-reduce its 1024 dists, then ballot-compact codes
// with dist <= min + MARGIN (sound: MARGIN >> 2x approx error bound ~1e-2).
__global__ void collect_kernel(void){
    int w = threadIdx.x >> 5, lane = threadIdx.x & 31;
    int n = blockIdx.x * 8 + w;
    const float4* row = (const float4*)(g_dist + (size_t)n * NE);

    float4 v[8];
    float mn = 1e30f;
    #pragma unroll
    for (int i = 0; i < 8; i++){
        v[i] = __ldg(row + i * 32 + lane);
        mn = fminf(mn, fminf(fminf(v[i].x, v[i].y), fminf(v[i].z, v[i].w)));
    }
    #pragma unroll
    for (int off = 16; off; off >>= 1)
        mn = fminf(mn, __shfl_xor_sync(0xffffffffu, mn, off));
    float thr = mn + MARGIN;

    int total = 0;
    #pragma unroll
    for (int i = 0; i < 8; i++){
        float vals[4] = {v[i].x, v[i].y, v[i].z, v[i].w};
        #pragma unroll
        for (int j = 0; j < 4; j++){
            bool p = vals[j] <= thr;
            unsigned msk = __ballot_sync(0xffffffffu, p);
            if (p){
                int pos = total + __popc(msk & ((1u << lane) - 1u));
                if (pos < 8) g_cand[n][pos] = (unsigned short)(((i * 32 + lane) << 2) + j);
            }
            total += __popc(msk);
        }
    }
    if (lane == 0) g_ccnt[n] = (unsigned char)(total > 255 ? 255 : total);
}

// -------------------- kernel 4: exact fp32 rescore of candidates --------------------
// Block: 64 tokens, 4 threads/token. Same exact-score + tie-break as R1 (passed).
__global__ void rescore_kernel(const float* __restrict__ z, const float* __restrict__ cb,
                               float* __restrict__ out){
    extern __shared__ char smem_raw[];
    float* zs = (float*)smem_raw;              // [256 k][64 tok]
    ull* keys = (ull*)(smem_raw + 65536);      // [64]
    int tid = threadIdx.x;
    int n0 = blockIdx.x << 6;
    int b = n0 >> 12, hw0 = n0 & 4095;
    const float* zb = z + (size_t)b * (EDIM * HW) + hw0;

    for (int i = tid; i < 4096; i += 256){
        int k = i >> 4, t4 = (i & 15) << 2;
        float4 v = *(const float4*)(zb + (size_t)k * HW + t4);
        *(float4*)(zs + k * 64 + t4) = v;
    }
    if (tid < 64) keys[tid] = ~0ULL;
    __syncthreads();

    int lt = tid >> 2, sub = tid & 3, n = n0 + lt;
    int cnt = g_ccnt[n];
    bool ovf = (cnt > 8) || (cnt == 0);

    ull bk = ~0ULL;
    int m = ovf ? NE : cnt;
    for (int ci = sub; ci < m; ci += 4){
        int code = ovf ? ci : (int)g_cand[n][ci];
        const float4* crow = (const float4*)(cb + (size_t)code * EDIM);
        float acc = 0.0f;
        #pragma unroll 8
        for (int kk = 0; kk < 64; kk++){
            float4 cv = __ldg(crow + kk);
            int k = kk << 2;
            acc = fmaf(cv.x, zs[k * 64 + lt], acc);
            acc = fmaf(cv.y, zs[(k + 1) * 64 + lt], acc);
            acc = fmaf(cv.z, zs[(k + 2) * 64 + lt], acc);
            acc = fmaf(cv.w, zs[(k + 3) * 64 + lt], acc);
        }
        float dist = __ldg(&g_cn[code]) - 2.0f * acc;
        ull key = ((ull)fenc(dist) << 32) | (unsigned)code;
        if (key < bk) bk = key;
    }
    if (bk != ~0ULL) atomicMin(&keys[lt], bk);
    __syncthreads();
    if (tid < 64){
        int idx = (int)(unsigned)(keys[tid] & 0xFFFFFFFFULL);
        g_idx[n0 + tid] = idx;
        out[OFF_IDX + n0 + tid] = (float)idx;
    }
}

// -------------------- kernel 5: gather z_q + loss partials --------------------
__global__ void gather_kernel(const float* __restrict__ z, const float* __restrict__ cb,
                              float* __restrict__ out){
    __shared__ float red[8];
    int t = blockIdx.x * 256 + threadIdx.x;
    int o4 = t << 2;
    int b = o4 >> 20;
    int rem = o4 & 1048575;
    int c = rem >> 12;
    int hw = rem & 4095;
    int n = (b << 12) + hw;

    float4 zv = *(const float4*)(z + o4);
    int i0 = g_idx[n], i1 = g_idx[n + 1], i2 = g_idx[n + 2], i3 = g_idx[n + 3];
    float4 q;
    q.x = __ldg(cb + (size_t)i0 * EDIM + c);
    q.y = __ldg(cb + (size_t)i1 * EDIM + c);
    q.z = __ldg(cb + (size_t)i2 * EDIM + c);
    q.w = __ldg(cb + (size_t)i3 * EDIM + c);
    *(float4*)(out + o4) = q;

    float dx = q.x - zv.x, dy = q.y - zv.y, dz = q.z - zv.z, dw = q.w - zv.w;
    float s = dx * dx + dy * dy + dz * dz + dw * dw;

    #pragma unroll
    for (int off = 16; off; off >>= 1) s += __shfl_down_sync(0xffffffffu, s, off);
    int lane = threadIdx.x & 31, wid = threadIdx.x >> 5;
    if (lane == 0) red[wid] = s;
    __syncthreads();
    if (wid == 0){
        float v = (lane < 8) ? red[lane] : 0.0f;
        #pragma unroll
        for (int off = 4; off; off >>= 1) v += __shfl_down_sync(0xffffffffu, v, off);
        if (lane == 0) g_part[blockIdx.x] = v;
    }
}

// -------------------- kernel 6: deterministic final loss reduction --------------------
__global__ void finalize_kernel(float* __restrict__ out){
    __shared__ float red[256];
    int tid = threadIdx.x;
    float s = 0.0f;
    for (int j = 0; j < 64; j++) s += g_part[tid + (j << 8)];
    red[tid] = s;
    __syncthreads();
    for (int st = 128; st > 0; st >>= 1){
        if (tid < st) red[tid] += red[tid + st];
        __syncthreads();
    }
    if (tid == 0){
        out[OFF_LOSS] = red[0] / 16777216.0f;
        out[OFF_ZERO] = 0.0f;
    }
}

// -------------------- launch --------------------
extern "C" void kernel_launch(void* const* d_in, const int* in_sizes, int n_in,
                              void* d_out, int out_size){
    const float* z  = (const float*)d_in[0];
    const float* cb = (const float*)d_in[1];
    if (n_in >= 2 && in_sizes[0] == NE * EDIM && in_sizes[1] == ZQ_ELEMS){
        const float* t = z; z = cb; cb = t;
    }
    float* out = (float*)d_out;

    cudaFuncSetAttribute(p1_kernel, cudaFuncAttributeMaxDynamicSharedMemorySize, P1_SMEM);
    cudaFuncSetAttribute(rescore_kernel, cudaFuncAttributeMaxDynamicSharedMemorySize, 66048);

    prep_cb_kernel<<<NE, 256>>>(cb);
    p1_kernel<<<N_TOK / 128, 256, P1_SMEM>>>(z);
    collect_kernel<<<N_TOK / 8, 256>>>();
    rescore_kernel<<<N_TOK / 64, 256, 66048>>>(z, cb, out);
    gather_kernel<<<ZQ_ELEMS / 1024, 256>>>(z, cb, out);
    finalize_kernel<<<1, 256>>>(out);
}

// round 15
// speedup vs baseline: 20.8598x; 1.0854x over previous
#include <cuda_runtime.h>
#include <cuda_bf16.h>
#include <cuda_fp16.h>
#include <cstdint>

#define EDIM 256
#define NE 1024
#define HW 4096
#define N_TOK 65536
#define ZQ_ELEMS 16777216
#define OFF_LOSS 16777216
#define OFF_ZERO 16777217
#define OFF_IDX  16777218
#define MARGIN2 2.0f

typedef unsigned long long ull;

// -------------------- device globals --------------------
__device__ __nv_bfloat16 g_ch[NE * EDIM];    // codebook bf16
__device__ float g_cn[NE];                   // ||c||^2 fp32
__device__ unsigned short g_cand[N_TOK][8];  // candidate codes per token
__device__ unsigned char  g_ccnt[N_TOK];     // candidate count per token
__device__ int   g_idx[N_TOK];
__device__ float g_part[16384];

__device__ __forceinline__ unsigned fenc(float x){
    unsigned u = __float_as_uint(x);
    return (u & 0x80000000u) ? ~u : (u | 0x80000000u);
}
__device__ __forceinline__ float fdec(unsigned e){
    unsigned u = (e & 0x80000000u) ? (e & 0x7FFFFFFFu) : ~e;
    return __uint_as_float(u);
}

// mma.sync m16n8k16 bf16 -> f32 (Ampere-era PTX; valid on plain sm_103 target)
#define MMA16816(c, a, b) \
    asm volatile("mma.sync.aligned.m16n8k16.row.col.f32.bf16.bf16.f32 " \
        "{%0,%1,%2,%3}, {%4,%5,%6,%7}, {%8,%9}, {%0,%1,%2,%3};" \
        : "+f"((c)[0]), "+f"((c)[1]), "+f"((c)[2]), "+f"((c)[3]) \
        : "r"((a)[0]), "r"((a)[1]), "r"((a)[2]), "r"((a)[3]), \
          "r"((b)[0]), "r"((b)[1]))

// -------------------- smem layout for p1 (byte offsets) --------------------
// z/c tiles: row stride 264 bf16 = 528 B = 132 words (conflict-light frag loads)
// dist tile: row stride 1056 fp16 = 2112 B
#define S2_ZH   0          // 64 x 528             = 33792
#define S2_CH   33792      // 64 x 528             = 33792
#define S2_DIST 67584      // 64 x 2112            = 135168
#define S2_TMIN 202752     // 64 x 4               = 256
#define P2_SMEM 203008

// -------------------- kernel 1: codebook prep (bf16 + norms) --------------------
__global__ void prep_cb_kernel(const float* __restrict__ cb){
    __shared__ float red[256];
    int code = blockIdx.x, k = threadIdx.x;
    float v = cb[code * EDIM + k];
    g_ch[code * EDIM + k] = __float2bfloat16(v);
    red[k] = v * v;
    __syncthreads();
    for (int s = 128; s > 0; s >>= 1){
        if (k < s) red[k] += red[k + s];
        __syncthreads();
    }
    if (k == 0) g_cn[code] = red[0];
}

// -------------------- kernel 2: fused HMMA shortlist (single product, final-min margin) ----
// Block: 64 tokens x ALL 1024 codes (16 passes of 64). 8 warps = 4(M) x 2(N).
// dist~ = ||c||^2 - 2 * (zh . ch)   (err <= ~0.3 absolute; MARGIN2=2.0 >> 2*err)
// fp16 distances kept in smem; per-token fp32 min via atomicMin(fenc);
// one-thread-per-token scan emits candidates. No gmem dist spill.
// (Fragment indexing + acc mapping identical to the R9-validated kernel.)
__global__ __launch_bounds__(256, 1)
void p1_kernel(const float* __restrict__ z){
    extern __shared__ char sm[];
    uint32_t* zh32 = (uint32_t*)(sm + S2_ZH);
    uint32_t* ch32 = (uint32_t*)(sm + S2_CH);
    unsigned* tmin = (unsigned*)(sm + S2_TMIN);

    const int tid = threadIdx.x;
    const int lane = tid & 31, wid = tid >> 5;
    const int gid = lane >> 2, tig = lane & 3;
    const int wm = wid & 3, wn = wid >> 2;

    const int n0 = blockIdx.x << 6;
    const int b = n0 >> 12, hw0 = n0 & 4095;
    const float* zb = z + (size_t)b * (EDIM * HW) + hw0;

    if (tid < 64) tmin[tid] = 0xFFFFFFFFu;

    // build z bf16 tile [64 tok][256 k], stride 528 B
    for (int i = tid; i < 4096; i += 256){
        int k = i >> 4, t4 = (i & 15) << 2;
        float4 v = *(const float4*)(zb + (size_t)k * HW + t4);
        float vv[4] = {v.x, v.y, v.z, v.w};
        #pragma unroll
        for (int j = 0; j < 4; j++)
            *(__nv_bfloat16*)(sm + S2_ZH + (t4 + j) * 528 + k * 2) = __float2bfloat16(vv[j]);
    }

    for (int pass = 0; pass < 16; pass++){
        __syncthreads();   // prev pass's ch reads done (and pass0: z/ch tile ordering)
        // load 64-code ch tile
        {
            int row = tid >> 2, kc = (tid & 3) << 6;
            const uint4* sh = (const uint4*)(g_ch + (size_t)(pass * 64 + row) * EDIM + kc);
            uint4* dh = (uint4*)(sm + S2_CH + row * 528 + kc * 2);
            #pragma unroll
            for (int i = 0; i < 8; i++) dh[i] = sh[i];
        }
        __syncthreads();

        float acc[4][4];
        #pragma unroll
        for (int nt = 0; nt < 4; nt++)
            #pragma unroll
            for (int r = 0; r < 4; r++) acc[nt][r] = 0.0f;

        #pragma unroll 4
        for (int ks = 0; ks < 16; ks++){
            uint32_t ah[4];
            int r0 = (wm * 16 + gid) * 132 + ks * 8 + tig;
            ah[0] = zh32[r0];
            ah[1] = zh32[r0 + 8 * 132];
            ah[2] = zh32[r0 + 4];
            ah[3] = zh32[r0 + 8 * 132 + 4];
            uint32_t bh[4][2];
            #pragma unroll
            for (int nt = 0; nt < 4; nt++){
                int c0 = (wn * 32 + nt * 8 + gid) * 132 + ks * 8 + tig;
                bh[nt][0] = ch32[c0];
                bh[nt][1] = ch32[c0 + 4];
            }
            #pragma unroll
            for (int nt = 0; nt < 4; nt++)
                MMA16816(acc[nt], ah, bh[nt]);
        }

        // epilogue: fp16 dists to smem + per-token fp32 running block-min
        #pragma unroll
        for (int rp = 0; rp < 2; rp++){
            int tl = wm * 16 + gid + rp * 8;
            float rmin = 1e30f;
            #pragma unroll
            for (int nt = 0; nt < 4; nt++){
                int code = pass * 64 + wn * 32 + nt * 8 + tig * 2;
                float d0 = __ldg(&g_cn[code])     - 2.0f * acc[nt][rp * 2];
                float d1 = __ldg(&g_cn[code + 1]) - 2.0f * acc[nt][rp * 2 + 1];
                rmin = fminf(rmin, fminf(d0, d1));
                *(__half2*)(sm + S2_DIST + tl * 2112 + code * 2) =
                    __floats2half2_rn(d0, d1);
            }
            atomicMin(&tmin[tl], fenc(rmin));
        }
    }
    __syncthreads();

    // scan: one thread per token, deterministic in-order candidate emit
    if (tid < 64){
        int tok = tid, n = n0 + tok;
        float thr = fdec(tmin[tok]) + MARGIN2;
        const __half2* row = (const __half2*)(sm + S2_DIST + tok * 2112);
        int cnt = 0;
        for (int w = 0; w < 512; w++){
            float2 f = __half22float2(row[w]);
            if (f.x <= thr){ if (cnt < 8) g_cand[n][cnt] = (unsigned short)(w * 2);     cnt++; }
            if (f.y <= thr){ if (cnt < 8) g_cand[n][cnt] = (unsigned short)(w * 2 + 1); cnt++; }
        }
        g_ccnt[n] = (unsigned char)(cnt > 255 ? 255 : cnt);
    }
}

// -------------------- kernel 3: exact fp32 rescore of candidates --------------------
// Block: 64 tokens, 4 threads/token. Same exact-score + tie-break as R1 (passed).
__global__ void rescore_kernel(const float* __restrict__ z, const float* __restrict__ cb,
                               float* __restrict__ out){
    extern __shared__ char smem_raw[];
    float* zs = (float*)smem_raw;              // [256 k][64 tok]
    ull* keys = (ull*)(smem_raw + 65536);      // [64]
    int tid = threadIdx.x;
    int n0 = blockIdx.x << 6;
    int b = n0 >> 12, hw0 = n0 & 4095;
    const float* zb = z + (size_t)b * (EDIM * HW) + hw0;

    for (int i = tid; i < 4096; i += 256){
        int k = i >> 4, t4 = (i & 15) << 2;
        float4 v = *(const float4*)(zb + (size_t)k * HW + t4);
        *(float4*)(zs + k * 64 + t4) = v;
    }
    if (tid < 64) keys[tid] = ~0ULL;
    __syncthreads();

    int lt = tid >> 2, sub = tid & 3, n = n0 + lt;
    int cnt = g_ccnt[n];
    bool ovf = (cnt > 8) || (cnt == 0);

    ull bk = ~0ULL;
    int m = ovf ? NE : cnt;
    for (int ci = sub; ci < m; ci += 4){
        int code = ovf ? ci : (int)g_cand[n][ci];
        const float4* crow = (const float4*)(cb + (size_t)code * EDIM);
        float acc = 0.0f;
        #pragma unroll 8
        for (int kk = 0; kk < 64; kk++){
            float4 cv = __ldg(crow + kk);
            int k = kk << 2;
            acc = fmaf(cv.x, zs[k * 64 + lt], acc);
            acc = fmaf(cv.y, zs[(k + 1) * 64 + lt], acc);
            acc = fmaf(cv.z, zs[(k + 2) * 64 + lt], acc);
            acc = fmaf(cv.w, zs[(k + 3) * 64 + lt], acc);
        }
        float dist = __ldg(&g_cn[code]) - 2.0f * acc;
        ull key = ((ull)fenc(dist) << 32) | (unsigned)code;
        if (key < bk) bk = key;
    }
    if (bk != ~0ULL) atomicMin(&keys[lt], bk);
    __syncthreads();
    if (tid < 64){
        int idx = (int)(unsigned)(keys[tid] & 0xFFFFFFFFULL);
        g_idx[n0 + tid] = idx;
        out[OFF_IDX + n0 + tid] = (float)idx;
    }
}

// -------------------- kernel 4: gather z_q + loss partials --------------------
__global__ void gather_kernel(const float* __restrict__ z, const float* __restrict__ cb,
                              float* __restrict__ out){
    __shared__ float red[8];
    int t = blockIdx.x * 256 + threadIdx.x;
    int o4 = t << 2;
    int b = o4 >> 20;
    int rem = o4 & 1048575;
    int c = rem >> 12;
    int hw = rem & 4095;
    int n = (b << 12) + hw;

    float4 zv = *(const float4*)(z + o4);
    int i0 = g_idx[n], i1 = g_idx[n + 1], i2 = g_idx[n + 2], i3 = g_idx[n + 3];
    float4 q;
    q.x = __ldg(cb + (size_t)i0 * EDIM + c);
    q.y = __ldg(cb + (size_t)i1 * EDIM + c);
    q.z = __ldg(cb + (size_t)i2 * EDIM + c);
    q.w = __ldg(cb + (size_t)i3 * EDIM + c);
    *(float4*)(out + o4) = q;

    float dx = q.x - zv.x, dy = q.y - zv.y, dz = q.z - zv.z, dw = q.w - zv.w;
    float s = dx * dx + dy * dy + dz * dz + dw * dw;

    #pragma unroll
    for (int off = 16; off; off >>= 1) s += __shfl_down_sync(0xffffffffu, s, off);
    int lane = threadIdx.x & 31, wid = threadIdx.x >> 5;
    if (lane == 0) red[wid] = s;
    __syncthreads();
    if (wid == 0){
        float v = (lane < 8) ? red[lane] : 0.0f;
        #pragma unroll
        for (int off = 4; off; off >>= 1) v += __shfl_down_sync(0xffffffffu, v, off);
        if (lane == 0) g_part[blockIdx.x] = v;
    }
}

// -------------------- kernel 5: deterministic final loss reduction --------------------
__global__ void finalize_kernel(float* __restrict__ out){
    __shared__ float red[256];
    int tid = threadIdx.x;
    float s = 0.0f;
    for (int j = 0; j < 64; j++) s += g_part[tid + (j << 8)];
    red[tid] = s;
    __syncthreads();
    for (int st = 128; st > 0; st >>= 1){
        if (tid < st) red[tid] += red[tid + st];
        __syncthreads();
    }
    if (tid == 0){
        out[OFF_LOSS] = red[0] / 16777216.0f;
        out[OFF_ZERO] = 0.0f;
    }
}

// -------------------- launch --------------------
extern "C" void kernel_launch(void* const* d_in, const int* in_sizes, int n_in,
                              void* d_out, int out_size){
    const float* z  = (const float*)d_in[0];
    const float* cb = (const float*)d_in[1];
    if (n_in >= 2 && in_sizes[0] == NE * EDIM && in_sizes[1] == ZQ_ELEMS){
        const float* t = z; z = cb; cb = t;
    }
    float* out = (float*)d_out;

    cudaFuncSetAttribute(p1_kernel, cudaFuncAttributeMaxDynamicSharedMemorySize, P2_SMEM);
    cudaFuncSetAttribute(rescore_kernel, cudaFuncAttributeMaxDynamicSharedMemorySize, 66048);

    prep_cb_kernel<<<NE, 256>>>(cb);
    p1_kernel<<<N_TOK / 64, 256, P2_SMEM>>>(z);
    rescore_kernel<<<N_TOK / 64, 256, 66048>>>(z, cb, out);
    gather_kernel<<<ZQ_ELEMS / 1024, 256>>>(z, cb, out);
    finalize_kernel<<<1, 256>>>(out);
}